// round 7
// baseline (speedup 1.0000x reference)
#include <cuda_runtime.h>
#include <math.h>

// Celerite (single-term Exp kernel, multiband amplitudes) log-likelihood.
// 2 launches, SEG_LEN=8, 2 segments/thread (ILP-2 chains), TPB=128:
//   kA: per-segment Mobius composition (w = 1/sigma2 - cS coords, all-positive
//       matrices) + in-block scan -> per-seg exclusive prefix + block composite
//   kC: per-block redundant scan of block composites -> exact w_in; exact
//       recurrence (2 indep chains) -> affine (A,B) + quad (Q0,Qcd,Q2);
//       in-block affine scan; quad expanded through in-block prefix into
//       per-block coefficients C0,C1,C2; last block (ticket) finishes.

#define TPB   128
#define NWARP (TPB / 32)
#define SEG_LEN 8
#define SPT   2                       // segments per thread
#define SEGS_PER_BLOCK (TPB * SPT)    // 256
#define MAX_SEG 262144
#define MAX_BLK 2048

__device__ float4 g_segPrefM[MAX_SEG];  // in-block exclusive Mobius prefix
__device__ float4 g_blockM[MAX_BLK];    // per-block Mobius composite
__device__ float2 g_blockA[MAX_BLK];    // per-block affine composite
__device__ double g_blkC0[MAX_BLK], g_blkC1[MAX_BLK], g_blkC2[MAX_BLK];
__device__ double g_partLd[MAX_BLK];
__device__ int    g_done = 0;           // self-resetting ticket

__device__ __forceinline__ float pick_amp(int b, float a1, float a2, float a3) {
    float u = 1.0f;
    u = (b == 1) ? a1 : u;
    u = (b == 2) ? a2 : u;
    u = (b == 3) ? a3 : u;
    return u;
}

__device__ __forceinline__ float fast_rcp(float x) { return __fdividef(1.0f, x); }

// n = later * earlier, normalized so n11 = 1 (entries >= 0: no cancellation)
__device__ __forceinline__ float4 mob_mul_norm(float4 l, float4 e) {
    float n00 = fmaf(l.x, e.x, l.y * e.z);
    float n01 = fmaf(l.x, e.y, l.y * e.w);
    float n10 = fmaf(l.z, e.x, l.w * e.z);
    float n11 = fmaf(l.z, e.y, l.w * e.w);
    float rn  = fast_rcp(n11);
    return make_float4(n00 * rn, n01 * rn, n10 * rn, 1.0f);
}

__device__ __forceinline__ float2 aff_mul(float2 l, float2 e) {
    return make_float2(l.x * e.x, fmaf(l.x, e.y, l.y));
}

// Block-wide INCLUSIVE Mobius scan via warp shuffles; sm[] filled, synced.
// NOTE: whole warp 0 executes the cross-warp shuffles (identity padding).
__device__ __forceinline__ void block_scan_mob(float4 v, float4* sm, float4* wb, int tid)
{
    int lane = tid & 31, wid = tid >> 5;
    #pragma unroll
    for (int d = 1; d < 32; d <<= 1) {
        float4 o;
        o.x = __shfl_up_sync(0xffffffffu, v.x, d);
        o.y = __shfl_up_sync(0xffffffffu, v.y, d);
        o.z = __shfl_up_sync(0xffffffffu, v.z, d);
        o.w = __shfl_up_sync(0xffffffffu, v.w, d);
        if (lane >= d) v = mob_mul_norm(v, o);
    }
    if (lane == 31) wb[wid] = v;
    __syncthreads();
    if (wid == 0) {
        float4 wv = (lane < NWARP) ? wb[lane] : make_float4(1.f, 0.f, 0.f, 1.f);
        #pragma unroll
        for (int d = 1; d < NWARP; d <<= 1) {
            float4 o;
            o.x = __shfl_up_sync(0xffffffffu, wv.x, d);
            o.y = __shfl_up_sync(0xffffffffu, wv.y, d);
            o.z = __shfl_up_sync(0xffffffffu, wv.z, d);
            o.w = __shfl_up_sync(0xffffffffu, wv.w, d);
            if (lane >= d) wv = mob_mul_norm(wv, o);
        }
        if (lane < NWARP) wb[lane] = wv;
    }
    __syncthreads();
    if (wid > 0) v = mob_mul_norm(v, wb[wid - 1]);
    sm[tid] = v;
    __syncthreads();
}

// Block-wide INCLUSIVE affine scan (same contract).
__device__ __forceinline__ void block_scan_aff(float2 v, float2* sm, float2* wb, int tid)
{
    int lane = tid & 31, wid = tid >> 5;
    #pragma unroll
    for (int d = 1; d < 32; d <<= 1) {
        float2 o;
        o.x = __shfl_up_sync(0xffffffffu, v.x, d);
        o.y = __shfl_up_sync(0xffffffffu, v.y, d);
        if (lane >= d) v = aff_mul(v, o);
    }
    if (lane == 31) wb[wid] = v;
    __syncthreads();
    if (wid == 0) {
        float2 wv = (lane < NWARP) ? wb[lane] : make_float2(1.f, 0.f);
        #pragma unroll
        for (int d = 1; d < NWARP; d <<= 1) {
            float2 o;
            o.x = __shfl_up_sync(0xffffffffu, wv.x, d);
            o.y = __shfl_up_sync(0xffffffffu, wv.y, d);
            if (lane >= d) wv = aff_mul(wv, o);
        }
        if (lane < NWARP) wb[lane] = wv;
    }
    __syncthreads();
    if (wid > 0) v = aff_mul(v, wb[wid - 1]);
    sm[tid] = v;
    __syncthreads();
}

// Block reduce of a double; result valid on tid 0.
__device__ __forceinline__ double blk_red(double v, double* s, int tid)
{
    #pragma unroll
    for (int d = 16; d > 0; d >>= 1)
        v += __shfl_down_sync(0xffffffffu, v, d);
    if ((tid & 31) == 0) s[tid >> 5] = v;
    __syncthreads();
    double r = 0.0;
    if (tid == 0) {
        #pragma unroll
        for (int k = 0; k < NWARP; ++k) r += s[k];
    }
    __syncthreads();
    return r;
}

// one Mobius element step (matrix pre-scaled by 1/Dt)
__device__ __forceinline__ void mob_step(
    float4& R, float ti, int b, float ye, float& prev_t, bool first,
    float sigma2, float inv_sigma2, float two_nie, float a1, float a2, float a3)
{
    float u  = pick_amp(b, a1, a2, a3);
    float U  = sigma2 * u;
    float e2 = ye * ye;
    float omp2 = first ? 1.0f : -expm1f(two_nie * (ti - prev_t));
    float p2 = 1.0f - omp2;
    prev_t = ti;
    float Dt    = fmaf(U * u, omp2, e2);
    float invDt = fast_rcp(Dt);
    float m00 = p2 * e2 * invDt;
    float m01 = inv_sigma2 * e2 * omp2 * invDt;
    float m10 = U * U * p2 * invDt;
    float n00 = fmaf(m00, R.x, m01 * R.z);
    float n01 = fmaf(m00, R.y, m01 * R.w);
    float n10 = fmaf(m10, R.x, R.z);
    float n11 = fmaf(m10, R.y, R.w);
    R = make_float4(n00, n01, n10, n11);
}

__device__ __forceinline__ void mob_renorm(float4& R) {
    float rn = fast_rcp(R.w);
    R = make_float4(R.x * rn, R.y * rn, R.z * rn, 1.0f);
}

// one exact recurrence step
__device__ __forceinline__ void cel_step(
    float ti, int b, float ye, float yi, float& prev_t, bool first,
    float sigma2, float inv_sigma2, float two_nie, float a1, float a2, float a3,
    float& w, float& A, float& Bv, float& q0, float& qcd, float& q2, float& ld)
{
    float u  = pick_amp(b, a1, a2, a3);
    float U  = sigma2 * u;
    float e2 = ye * ye;
    float omp2 = first ? 1.0f : -expm1f(two_nie * (ti - prev_t));
    float p2 = 1.0f - omp2;
    prev_t = ti;
    float p    = sqrtf(p2);             // exp(nie*dt); 0 when first
    float Dt   = fmaf(U * u, omp2, e2);
    float D    = fmaf(U * U * p2, w, Dt);
    float invD = fast_rcp(D);
    float W    = fmaf(U * p2, w, u * omp2) * invD;
    ld += __logf(D);
    float Up = U * p;
    float c  = fmaf(-Up, Bv, yi);
    float dd = Up * A;
    q0  = fmaf(c * invD, c, q0);
    qcd = fmaf(c * invD, dd, qcd);
    q2  = fmaf(dd * invD, dd, q2);
    float Astep = p * fmaf(-W, U, 1.0f);
    Bv = fmaf(Astep, Bv, W * yi);
    A *= Astep;
    w  = e2 * fmaf(p2, w, inv_sigma2 * omp2) * invD;
}

// ------------------- kA: segment Mobius + in-block scan -------------------
__global__ void __launch_bounds__(TPB, 7) kA_mobius(
    const float* __restrict__ t, const int* __restrict__ band,
    const float* __restrict__ yerr,
    const float* __restrict__ lad, const float* __restrict__ lkp,
    int N, int nseg)
{
    __shared__ float4 sm[TPB];
    __shared__ float4 wb[NWARP];
    int tid = threadIdx.x;
    int seg0 = blockIdx.x * SEGS_PER_BLOCK + 2 * tid;

    float sigma2 = expf(2.0f * lkp[0]);
    float inv_sigma2 = 1.0f / sigma2;
    float two_nie = -2.0f / expf(lkp[1]);
    float a1 = expf(lad[0]), a2 = expf(lad[1]), a3 = expf(lad[2]);

    float4 M0 = make_float4(1.f, 0.f, 0.f, 1.f);
    float4 M1 = make_float4(1.f, 0.f, 0.f, 1.f);

    int base = seg0 * SEG_LEN;
    if (seg0 + 1 < nseg && base + 2 * SEG_LEN <= N) {
        const float4* tp = (const float4*)(t + base);
        const int4*   bp = (const int4*)(band + base);
        const float4* ep = (const float4*)(yerr + base);
        float prev0 = (base > 0) ? __ldg(t + base - 1) : 0.0f;
        float prev1 = __ldg(t + base + SEG_LEN - 1);
        bool first0 = (base == 0);

        float4 T0 = __ldg(tp + 0), T2 = __ldg(tp + 2);
        int4   B0 = __ldg(bp + 0), B2 = __ldg(bp + 2);
        float4 E0 = __ldg(ep + 0), E2 = __ldg(ep + 2);
        mob_step(M0, T0.x, B0.x, E0.x, prev0, first0, sigma2, inv_sigma2, two_nie, a1, a2, a3);
        mob_step(M1, T2.x, B2.x, E2.x, prev1, false,  sigma2, inv_sigma2, two_nie, a1, a2, a3);
        mob_step(M0, T0.y, B0.y, E0.y, prev0, false,  sigma2, inv_sigma2, two_nie, a1, a2, a3);
        mob_step(M1, T2.y, B2.y, E2.y, prev1, false,  sigma2, inv_sigma2, two_nie, a1, a2, a3);
        mob_step(M0, T0.z, B0.z, E0.z, prev0, false,  sigma2, inv_sigma2, two_nie, a1, a2, a3);
        mob_step(M1, T2.z, B2.z, E2.z, prev1, false,  sigma2, inv_sigma2, two_nie, a1, a2, a3);
        mob_step(M0, T0.w, B0.w, E0.w, prev0, false,  sigma2, inv_sigma2, two_nie, a1, a2, a3);
        mob_step(M1, T2.w, B2.w, E2.w, prev1, false,  sigma2, inv_sigma2, two_nie, a1, a2, a3);
        float4 T1 = __ldg(tp + 1), T3 = __ldg(tp + 3);
        int4   B1 = __ldg(bp + 1), B3 = __ldg(bp + 3);
        float4 E1 = __ldg(ep + 1), E3 = __ldg(ep + 3);
        mob_step(M0, T1.x, B1.x, E1.x, prev0, false, sigma2, inv_sigma2, two_nie, a1, a2, a3);
        mob_step(M1, T3.x, B3.x, E3.x, prev1, false, sigma2, inv_sigma2, two_nie, a1, a2, a3);
        mob_step(M0, T1.y, B1.y, E1.y, prev0, false, sigma2, inv_sigma2, two_nie, a1, a2, a3);
        mob_step(M1, T3.y, B3.y, E3.y, prev1, false, sigma2, inv_sigma2, two_nie, a1, a2, a3);
        mob_step(M0, T1.z, B1.z, E1.z, prev0, false, sigma2, inv_sigma2, two_nie, a1, a2, a3);
        mob_step(M1, T3.z, B3.z, E3.z, prev1, false, sigma2, inv_sigma2, two_nie, a1, a2, a3);
        mob_step(M0, T1.w, B1.w, E1.w, prev0, false, sigma2, inv_sigma2, two_nie, a1, a2, a3);
        mob_step(M1, T3.w, B3.w, E3.w, prev1, false, sigma2, inv_sigma2, two_nie, a1, a2, a3);
        mob_renorm(M0);
        mob_renorm(M1);
    } else {
        // guarded scalar path
        for (int s = 0; s < SPT; ++s) {
            int seg = seg0 + s;
            if (seg >= nseg) break;
            int st = seg * SEG_LEN;
            int en = min(st + SEG_LEN, N);
            float prev = (st > 0) ? __ldg(t + st - 1) : 0.0f;
            float4 M = make_float4(1.f, 0.f, 0.f, 1.f);
            for (int i = st; i < en; ++i) {
                mob_step(M, __ldg(t + i), __ldg(band + i), __ldg(yerr + i),
                         prev, i == 0, sigma2, inv_sigma2, two_nie, a1, a2, a3);
                mob_renorm(M);
            }
            if (s == 0) M0 = M; else M1 = M;
        }
    }

    float4 Mc = mob_mul_norm(M1, M0);
    block_scan_mob(Mc, sm, wb, tid);

    float4 e = (tid == 0) ? make_float4(1.f, 0.f, 0.f, 1.f) : sm[tid - 1];
    if (seg0 < nseg)     g_segPrefM[seg0]     = e;
    if (seg0 + 1 < nseg) g_segPrefM[seg0 + 1] = mob_mul_norm(M0, e);
    if (tid == TPB - 1)  g_blockM[blockIdx.x] = sm[tid];
}

// ------------------- kC: recurrence + affine scan + fused finalization ------
__global__ void __launch_bounds__(TPB, 7) kC_seg(
    const float* __restrict__ t, const int* __restrict__ band,
    const float* __restrict__ y, const float* __restrict__ yerr,
    const float* __restrict__ lad, const float* __restrict__ lkp,
    float* __restrict__ out, int N, int nseg, int nblk)
{
    __shared__ float4 sm4[TPB];
    __shared__ float4 wb4[NWARP];
    __shared__ float2 sa[TPB];
    __shared__ float2 wb2[NWARP];
    __shared__ double sred[NWARP];
    __shared__ bool s_last;
    int tid = threadIdx.x;
    int seg0 = blockIdx.x * SEGS_PER_BLOCK + 2 * tid;

    // --- redundant scan of block Mobius composites -> this block's excl prefix
    int C = (nblk + TPB - 1) / TPB;
    {
        float4 r = make_float4(1.f, 0.f, 0.f, 1.f);
        int s0 = tid * C, s1 = min(s0 + C, nblk);
        for (int k = s0; k < s1; ++k) r = mob_mul_norm(g_blockM[k], r);
        block_scan_mob(r, sm4, wb4, tid);
    }
    float4 mb = make_float4(1.f, 0.f, 0.f, 1.f);
    {
        int bq = blockIdx.x / C;
        int br = blockIdx.x % C;
        if (bq > 0) mb = sm4[bq - 1];
        int s0 = bq * C;
        for (int k = s0; k < s0 + br; ++k) mb = mob_mul_norm(g_blockM[k], mb);
    }
    __syncthreads();

    float sigma2 = expf(2.0f * lkp[0]);
    float inv_sigma2 = 1.0f / sigma2;
    float two_nie = -2.0f / expf(lkp[1]);
    float a1 = expf(lad[0]), a2 = expf(lad[1]), a3 = expf(lad[2]);
    float w0c = inv_sigma2;

    float A0 = 1.f, B0v = 0.f, A1 = 1.f, B1v = 0.f;
    float q00 = 0.f, qcd0 = 0.f, q20 = 0.f;
    float q01 = 0.f, qcd1 = 0.f, q21 = 0.f;
    float ld = 0.f;

    int base = seg0 * SEG_LEN;
    if (seg0 + 1 < nseg && base + 2 * SEG_LEN <= N) {
        float4 tot0 = mob_mul_norm(g_segPrefM[seg0], mb);
        float4 tot1 = mob_mul_norm(g_segPrefM[seg0 + 1], mb);
        float w_0 = fmaf(tot0.x, w0c, tot0.y) / fmaf(tot0.z, w0c, tot0.w);
        float w_1 = fmaf(tot1.x, w0c, tot1.y) / fmaf(tot1.z, w0c, tot1.w);

        const float4* tp = (const float4*)(t + base);
        const int4*   bp = (const int4*)(band + base);
        const float4* yp = (const float4*)(y + base);
        const float4* ep = (const float4*)(yerr + base);
        float prev0 = (base > 0) ? __ldg(t + base - 1) : 0.0f;
        float prev1 = __ldg(t + base + SEG_LEN - 1);
        bool first0 = (base == 0);

        #pragma unroll
        for (int r = 0; r < 2; ++r) {
            float4 Ta = __ldg(tp + r),     Tb = __ldg(tp + r + 2);
            int4   Ba = __ldg(bp + r),     Bb = __ldg(bp + r + 2);
            float4 Ya = __ldg(yp + r),     Yb = __ldg(yp + r + 2);
            float4 Ea = __ldg(ep + r),     Eb = __ldg(ep + r + 2);
            float tav[4] = {Ta.x, Ta.y, Ta.z, Ta.w};
            int   bav[4] = {Ba.x, Ba.y, Ba.z, Ba.w};
            float yav[4] = {Ya.x, Ya.y, Ya.z, Ya.w};
            float eav[4] = {Ea.x, Ea.y, Ea.z, Ea.w};
            float tbv[4] = {Tb.x, Tb.y, Tb.z, Tb.w};
            int   bbv[4] = {Bb.x, Bb.y, Bb.z, Bb.w};
            float ybv[4] = {Yb.x, Yb.y, Yb.z, Yb.w};
            float ebv[4] = {Eb.x, Eb.y, Eb.z, Eb.w};
            #pragma unroll
            for (int e = 0; e < 4; ++e) {
                bool f0 = first0 && (r == 0) && (e == 0);
                cel_step(tav[e], bav[e], eav[e], yav[e], prev0, f0,
                         sigma2, inv_sigma2, two_nie, a1, a2, a3,
                         w_0, A0, B0v, q00, qcd0, q20, ld);
                cel_step(tbv[e], bbv[e], ebv[e], ybv[e], prev1, false,
                         sigma2, inv_sigma2, two_nie, a1, a2, a3,
                         w_1, A1, B1v, q01, qcd1, q21, ld);
            }
        }
    } else if (seg0 < nseg) {
        // guarded scalar path
        for (int s = 0; s < SPT; ++s) {
            int seg = seg0 + s;
            if (seg >= nseg) break;
            float4 tot = mob_mul_norm(g_segPrefM[seg], mb);
            float w = fmaf(tot.x, w0c, tot.y) / fmaf(tot.z, w0c, tot.w);
            int st = seg * SEG_LEN;
            int en = min(st + SEG_LEN, N);
            float prev = (st > 0) ? __ldg(t + st - 1) : 0.0f;
            float Aa = 1.f, Bb = 0.f, a_q0 = 0.f, a_qcd = 0.f, a_q2 = 0.f;
            for (int i = st; i < en; ++i) {
                cel_step(__ldg(t + i), __ldg(band + i), __ldg(yerr + i), __ldg(y + i),
                         prev, i == 0, sigma2, inv_sigma2, two_nie, a1, a2, a3,
                         w, Aa, Bb, a_q0, a_qcd, a_q2, ld);
            }
            if (s == 0) { A0 = Aa; B0v = Bb; q00 = a_q0; qcd0 = a_qcd; q20 = a_q2; }
            else        { A1 = Aa; B1v = Bb; q01 = a_q0; qcd1 = a_qcd; q21 = a_q2; }
        }
    }

    // in-block affine scan over thread composites
    float2 P0 = make_float2(A0, B0v);
    float2 P1 = make_float2(A1, B1v);
    float2 Pc = aff_mul(P1, P0);
    block_scan_aff(Pc, sa, wb2, tid);
    float2 ea = (tid == 0) ? make_float2(1.f, 0.f) : sa[tid - 1];
    if (tid == TPB - 1) g_blockA[blockIdx.x] = sa[tid];

    // quad expansion through in-block prefixes: coefficients in cg_block
    double c0 = 0.0, c1 = 0.0, c2 = 0.0;
    {
        float2 pr0 = ea;                 // prefix for seg0
        float2 pr1 = aff_mul(P0, ea);    // prefix for seg1
        float a = pr0.x, b = pr0.y;
        c0 += (double)fmaf(fmaf(q20, b, -2.0f * qcd0), b, q00);
        c1 += (double)(2.0f * a * fmaf(q20, b, -qcd0));
        c2 += (double)(q20 * a * a);
        a = pr1.x; b = pr1.y;
        c0 += (double)fmaf(fmaf(q21, b, -2.0f * qcd1), b, q01);
        c1 += (double)(2.0f * a * fmaf(q21, b, -qcd1));
        c2 += (double)(q21 * a * a);
    }

    double rld = blk_red((double)ld, sred, tid);
    double rc0 = blk_red(c0, sred, tid);
    double rc1 = blk_red(c1, sred, tid);
    double rc2 = blk_red(c2, sred, tid);
    if (tid == 0) {
        g_partLd[blockIdx.x] = rld;
        g_blkC0[blockIdx.x] = rc0;
        g_blkC1[blockIdx.x] = rc1;
        g_blkC2[blockIdx.x] = rc2;
    }
    __threadfence();
    __syncthreads();
    if (tid == 0) {
        int prev = atomicAdd(&g_done, 1);
        s_last = (prev == gridDim.x - 1);
    }
    __syncthreads();

    if (s_last) {
        // scan g_blockA (exclusive) and evaluate per-block quadratics
        float2 r = make_float2(1.f, 0.f);
        int s0 = tid * C, s1 = min(s0 + C, nblk);
        for (int k = s0; k < s1; ++k) r = aff_mul(g_blockA[k], r);
        block_scan_aff(r, sa, wb2, tid);
        float2 mbA = (tid == 0) ? make_float2(1.f, 0.f) : sa[tid - 1];
        double acc = 0.0;
        for (int k = s0; k < s1; ++k) {
            double cg = (double)mbA.y;    // cg entering block k (cg0 = 0)
            acc += g_blkC0[k] + cg * (g_blkC1[k] + cg * g_blkC2[k]) + g_partLd[k];
            mbA = aff_mul(g_blockA[k], mbA);
        }
        double tot = blk_red(acc, sred, tid);
        if (tid == 0) {
            double total = tot + (double)N * 1.837877066409345483560659472811;
            out[0] = (float)(-0.5 * total);
            atomicExch(&g_done, 0);      // self-reset for graph replay
        }
    }
}

extern "C" void kernel_launch(void* const* d_in, const int* in_sizes, int n_in,
                              void* d_out, int out_size)
{
    const float* t    = (const float*)d_in[0];
    const int*   band = (const int*)  d_in[1];
    const float* y    = (const float*)d_in[2];
    const float* yerr = (const float*)d_in[3];
    const float* lad  = (const float*)d_in[4];
    const float* lkp  = (const float*)d_in[5];
    float* out = (float*)d_out;

    int N = in_sizes[0];
    int nseg = (N + SEG_LEN - 1) / SEG_LEN;
    int nblk = (nseg + SEGS_PER_BLOCK - 1) / SEGS_PER_BLOCK;

    kA_mobius<<<nblk, TPB>>>(t, band, yerr, lad, lkp, N, nseg);
    kC_seg<<<nblk, TPB>>>(t, band, y, yerr, lad, lkp, out, N, nseg, nblk);
}